// round 16
// baseline (speedup 1.0000x reference)
#include <cuda_runtime.h>
#include <cuda_fp16.h>
#include <math.h>
#include <stdint.h>

#define B_ 384
#define Q_ 384
#define V_ 197
#define T_ 100
#define D_ 768
#define E_ 256
#define K_ 50
#define KP 64
#define MR (B_ * KP)
#define MPACK (B_ * K_)
#define NBY (MPACK / 128)      // 150

// ---------------- scratch (no allocations allowed) ----------------
__device__ float  g_vtok[B_*V_*E_];
__device__ float  g_ttok[Q_*T_*E_];
__device__ float  g_glob[2*B_*E_];
__device__ double g_vsim[B_*V_];
__device__ double g_tsim[Q_*T_];
__device__ float  g_vnf[B_*V_];
__device__ float  g_tnf[Q_*T_];
__device__ int    g_iv[B_*K_];
__device__ int    g_it[Q_*K_];
__device__ float  g_pI[NBY*4*Q_];
__device__ float  g_pC[(size_t)NBY*4*Q_*K_];
__device__ __align__(16) __half g_Avh[B_*V_*D_];
__device__ __align__(16) __half g_Avl[B_*V_*D_];
__device__ __align__(16) __half g_Ath[Q_*T_*D_];
__device__ __align__(16) __half g_Atl[Q_*T_*D_];
__device__ __align__(16) __half g_Acvh[B_*D_];
__device__ __align__(16) __half g_Acvl[B_*D_];
__device__ __align__(16) __half g_Acth[Q_*D_];
__device__ __align__(16) __half g_Actl[Q_*D_];
__device__ __align__(16) __half g_Wvh[E_*D_];
__device__ __align__(16) __half g_Wvl[E_*D_];
__device__ __align__(16) __half g_Wth[E_*D_];
__device__ __align__(16) __half g_Wtl[E_*D_];
__device__ __align__(16) __half g_Wvth[E_*D_];
__device__ __align__(16) __half g_Wvtl[E_*D_];
__device__ __align__(16) __half g_Wtth[E_*D_];
__device__ __align__(16) __half g_Wttl[E_*D_];
__device__ __align__(16) __half g_vhi[MR*E_];
__device__ __align__(16) __half g_thi[MR*E_];

// ================= PTX helpers =================
__device__ __forceinline__ uint32_t smem_u32(const void* p) {
    uint32_t a;
    asm("{ .reg .u64 t; cvta.to.shared.u64 t, %1; cvt.u32.u64 %0, t; }" : "=r"(a) : "l"(p));
    return a;
}
__device__ __forceinline__ void ldsm_x4(uint32_t* r, uint32_t addr) {
    asm volatile("ldmatrix.sync.aligned.m8n8.x4.shared.b16 {%0,%1,%2,%3}, [%4];"
                 : "=r"(r[0]), "=r"(r[1]), "=r"(r[2]), "=r"(r[3]) : "r"(addr));
}
__device__ __forceinline__ void mma16816(float* d, const uint32_t* a, uint32_t b0, uint32_t b1) {
    asm volatile(
        "mma.sync.aligned.m16n8k16.row.col.f32.f16.f16.f32 "
        "{%0,%1,%2,%3}, {%4,%5,%6,%7}, {%8,%9}, {%0,%1,%2,%3};"
        : "+f"(d[0]), "+f"(d[1]), "+f"(d[2]), "+f"(d[3])
        : "r"(a[0]), "r"(a[1]), "r"(a[2]), "r"(a[3]), "r"(b0), "r"(b1));
}
__device__ __forceinline__ void cp16(uint32_t dst, const void* src) {
    asm volatile("cp.async.cg.shared.global [%0], [%1], 16;" :: "r"(dst), "l"(src) : "memory");
}
#define CP_COMMIT() asm volatile("cp.async.commit_group;" ::: "memory")
#define CP_WAIT0()  asm volatile("cp.async.wait_group 0;" ::: "memory")

// ---------------- merged split: 4 input tensors + 4 transposed weights ----------------
#define N_VT (B_*V_*D_)
#define N_TT (Q_*T_*D_)
#define N_VC (B_*D_)
#define N_W  (D_*E_)
#define N_IN ((long)N_VT + N_TT + 2 * N_VC)
#define N_ALL (N_IN + 4L * N_W)
__global__ void split_all_kernel(const float* __restrict__ vt, const float* __restrict__ tt,
                                 const float* __restrict__ vc, const float* __restrict__ tc,
                                 const float* __restrict__ W0, const float* __restrict__ W1,
                                 const float* __restrict__ W2, const float* __restrict__ W3,
                                 __half* __restrict__ vth, __half* __restrict__ vtl,
                                 __half* __restrict__ tth, __half* __restrict__ ttl,
                                 __half* __restrict__ vch, __half* __restrict__ vcl,
                                 __half* __restrict__ tch, __half* __restrict__ tcl,
                                 __half* __restrict__ w0h, __half* __restrict__ w0l,
                                 __half* __restrict__ w1h, __half* __restrict__ w1l,
                                 __half* __restrict__ w2h, __half* __restrict__ w2l,
                                 __half* __restrict__ w3h, __half* __restrict__ w3l) {
    long i = (long)blockIdx.x * 256 + threadIdx.x;
    if (i >= N_ALL) return;
    if (i < N_IN) {
        const float* src; __half *hi, *lo; long o;
        if (i < N_VT)                          { src = vt; hi = vth; lo = vtl; o = i; }
        else if (i < (long)N_VT + N_TT)        { src = tt; hi = tth; lo = ttl; o = i - N_VT; }
        else if (i < (long)N_VT + N_TT + N_VC) { src = vc; hi = vch; lo = vcl; o = i - N_VT - N_TT; }
        else                                   { src = tc; hi = tch; lo = tcl; o = i - N_VT - N_TT - N_VC; }
        float a = src[o];
        __half h = __float2half(a);
        hi[o] = h;
        lo[o] = __float2half(a - __half2float(h));
    } else {
        long w = i - N_IN;
        int sel = (int)(w / N_W);
        long rem = w % N_W;
        int k = (int)(rem / E_), n = (int)(rem % E_);
        const float* W = (sel == 0) ? W0 : (sel == 1) ? W1 : (sel == 2) ? W2 : W3;
        __half* hiT = (sel == 0) ? w0h : (sel == 1) ? w1h : (sel == 2) ? w2h : w3h;
        __half* loT = (sel == 0) ? w0l : (sel == 1) ? w1l : (sel == 2) ? w2l : w3l;
        float a = W[k * E_ + n];
        __half h = __float2half(a);
        hiT[(size_t)n * D_ + k] = h;
        loT[(size_t)n * D_ + k] = __float2half(a - __half2float(h));
    }
}

// ================= merged projection GEMM on HMMA (all 4 GEMMs, one launch) ============
#define PSTG 32768
#define PMAT 8192
#define YB_VTOK ((B_ * V_) / 128)              // 591
#define YB_TTOK ((Q_ * T_) / 128)              // 300
#define YB_CLS  (B_ / 128)                     // 3
#define YB_TOTAL (YB_VTOK + YB_TTOK + 2 * YB_CLS)  // 897

struct ProjArgs {
    const __half *Ah[4], *Al[4], *Wh[4], *Wl[4];
    const float *bias[4];
    float *C[4];
};

__global__ void __launch_bounds__(256)
proj_mma_kernel(ProjArgs args) {
    extern __shared__ __align__(16) char dyn[];
    const uint32_t sbase = smem_u32(dyn);
    const int tid = threadIdx.x, wid = tid >> 5, lane = tid & 31;
    // blockIdx.y range -> which gemm + local m block (big ones first)
    int yb = blockIdx.y, g, mb;
    if (yb < YB_VTOK)                    { g = 0; mb = yb; }
    else if (yb < YB_VTOK + YB_TTOK)     { g = 1; mb = yb - YB_VTOK; }
    else if (yb < YB_VTOK + YB_TTOK + YB_CLS) { g = 2; mb = yb - YB_VTOK - YB_TTOK; }
    else                                 { g = 3; mb = yb - YB_VTOK - YB_TTOK - YB_CLS; }
    const int m0 = mb * 128, n0 = blockIdx.x * 128;
    const int warp_m = wid >> 1, warp_n = wid & 1;
    const __half* gmat[4] = { args.Ah[g] + (size_t)m0 * D_, args.Al[g] + (size_t)m0 * D_,
                              args.Wh[g] + (size_t)n0 * D_, args.Wl[g] + (size_t)n0 * D_ };
    const float* bias = args.bias[g];
    float* C = args.C[g];
    auto load_stage = [&](int ks, int buf) {
        uint32_t sb = sbase + buf * PSTG;
#pragma unroll
        for (int it = 0; it < 8; it++) {
            int idx = tid + it * 256;
            int mat = idx >> 9, rem = idx & 511;
            int r = rem >> 2, chunk = rem & 3;
            const void* src = gmat[mat] + (size_t)r * D_ + ks * 32 + chunk * 8;
            uint32_t dst = sb + mat * PMAT + r * 64 + ((chunk ^ (r & 3)) << 4);
            cp16(dst, src);
        }
        CP_COMMIT();
    };
    float acc[2][8][4] = {};
    load_stage(0, 0);
    for (int ks = 0; ks < 24; ks++) {
        CP_WAIT0();
        __syncthreads();
        if (ks + 1 < 24) load_stage(ks + 1, (ks + 1) & 1);
        uint32_t sb = sbase + (ks & 1) * PSTG;
        const int rA = warp_m * 32 + (lane & 15);
        const int khalf = lane >> 4;
#pragma unroll
        for (int kstep = 0; kstep < 2; kstep++) {
            uint32_t ah[2][4], al[2][4], wh[4][4], wl[4][4];
            int chunk = kstep * 2 + khalf;
#pragma unroll
            for (int mt = 0; mt < 2; mt++) {
                int r = rA + mt * 16;
                uint32_t off = r * 64 + ((chunk ^ (r & 3)) << 4);
                ldsm_x4(ah[mt], sb + 0 * PMAT + off);
                ldsm_x4(al[mt], sb + 1 * PMAT + off);
            }
#pragma unroll
            for (int nt = 0; nt < 4; nt++) {
                int r = warp_n * 64 + nt * 16 + (lane & 15);
                uint32_t off = r * 64 + ((chunk ^ (r & 3)) << 4);
                ldsm_x4(wh[nt], sb + 2 * PMAT + off);
                ldsm_x4(wl[nt], sb + 3 * PMAT + off);
            }
#pragma unroll
            for (int mt = 0; mt < 2; mt++)
#pragma unroll
                for (int nt = 0; nt < 4; nt++) {
                    mma16816(acc[mt][nt * 2 + 0], ah[mt], wh[nt][0], wh[nt][2]);
                    mma16816(acc[mt][nt * 2 + 1], ah[mt], wh[nt][1], wh[nt][3]);
                    mma16816(acc[mt][nt * 2 + 0], ah[mt], wl[nt][0], wl[nt][2]);
                    mma16816(acc[mt][nt * 2 + 1], ah[mt], wl[nt][1], wl[nt][3]);
                    mma16816(acc[mt][nt * 2 + 0], al[mt], wh[nt][0], wh[nt][2]);
                    mma16816(acc[mt][nt * 2 + 1], al[mt], wh[nt][1], wh[nt][3]);
                }
        }
        __syncthreads();
    }
#pragma unroll
    for (int mt = 0; mt < 2; mt++)
#pragma unroll
        for (int nt8 = 0; nt8 < 8; nt8++) {
            int row = m0 + warp_m * 32 + mt * 16 + (lane >> 2);
            int col = n0 + warp_n * 64 + nt8 * 8 + (lane & 3) * 2;
            C[(size_t)row * E_ + col]           = acc[mt][nt8][0] + bias[col];
            C[(size_t)row * E_ + col + 1]       = acc[mt][nt8][1] + bias[col + 1];
            C[(size_t)(row + 8) * E_ + col]     = acc[mt][nt8][2] + bias[col];
            C[(size_t)(row + 8) * E_ + col + 1] = acc[mt][nt8][3] + bias[col + 1];
        }
}

// ------- l2-normalize 768 contiguous cls rows (f64 norm, f32 division) -------
__global__ void norm_rows_kernel(const float* __restrict__ in, float* __restrict__ out) {
    int warp = (blockIdx.x * blockDim.x + threadIdx.x) >> 5;
    int lane = threadIdx.x & 31;
    const float* r = in + (size_t)warp * E_;
    float v[8]; double s = 0.0;
#pragma unroll
    for (int j = 0; j < 8; j++) { v[j] = r[j * 32 + lane]; s += (double)v[j] * (double)v[j]; }
#pragma unroll
    for (int o = 16; o > 0; o >>= 1) s += __shfl_xor_sync(0xffffffffu, s, o);
    float nf = fmaxf((float)sqrt(s), 1e-12f);
#pragma unroll
    for (int j = 0; j < 8; j++) out[(size_t)warp * E_ + j * 32 + lane] = v[j] / nf;
}

// ---- merged per-row norm (f64) + f64 dot-with-global sim for BOTH modalities ----
__global__ void tok_sim_kernel(const float* __restrict__ vtok, const float* __restrict__ ttok,
                               const float* __restrict__ glob,
                               double* __restrict__ vsim, double* __restrict__ tsim,
                               float* __restrict__ vnf, float* __restrict__ tnf) {
    int warp = (blockIdx.x * blockDim.x + threadIdx.x) >> 5;
    int lane = threadIdx.x & 31;
    const float* tok; double* sim; float* nfa; int gidx;
    if (warp < B_ * V_) {
        tok = vtok + (size_t)warp * E_; sim = vsim + warp; nfa = vnf + warp; gidx = warp / V_;
    } else {
        int w = warp - B_ * V_;
        tok = ttok + (size_t)w * E_; sim = tsim + w; nfa = tnf + w; gidx = B_ + w / T_;
    }
    float v[8]; double s = 0.0;
#pragma unroll
    for (int j = 0; j < 8; j++) { v[j] = tok[j * 32 + lane]; s += (double)v[j] * (double)v[j]; }
#pragma unroll
    for (int o = 16; o > 0; o >>= 1) s += __shfl_xor_sync(0xffffffffu, s, o);
    float nf = fmaxf((float)sqrt(s), 1e-12f);
    const float* g = glob + (size_t)gidx * E_;
    double d = 0.0;
#pragma unroll
    for (int j = 0; j < 8; j++) {
        float nv = v[j] / nf;
        d += (double)nv * (double)g[j * 32 + lane];
    }
#pragma unroll
    for (int o = 16; o > 0; o >>= 1) d += __shfl_xor_sync(0xffffffffu, d, o);
    if (lane == 0) { *sim = d; *nfa = nf; }
}

// ---------------- merged top-K (both modalities) ----------------
__global__ void topk_kernel(const double* __restrict__ vsim, const double* __restrict__ tsim,
                            int* __restrict__ iv, int* __restrict__ it) {
    __shared__ double vals[256];
    __shared__ double wv[8];
    __shared__ int wi[8];
    int blk = blockIdx.x;
    const double* sim; int* out; int n;
    if (blk < B_) { sim = vsim + (size_t)blk * V_; out = iv + blk * K_; n = V_; }
    else          { int b = blk - B_; sim = tsim + (size_t)b * T_; out = it + b * K_; n = T_; }
    int t = threadIdx.x;
    vals[t] = (t < n) ? sim[t] : -1e300;
    __syncthreads();
    for (int k = 0; k < K_; k++) {
        double v = vals[t]; int i = t;
#pragma unroll
        for (int o = 16; o > 0; o >>= 1) {
            double ov = __shfl_xor_sync(0xffffffffu, v, o);
            int oi = __shfl_xor_sync(0xffffffffu, i, o);
            if (ov > v || (ov == v && oi < i)) { v = ov; i = oi; }
        }
        if ((t & 31) == 0) { wv[t >> 5] = v; wi[t >> 5] = i; }
        __syncthreads();
        if (t == 0) {
            double bv = wv[0]; int bi = wi[0];
#pragma unroll
            for (int w = 1; w < 8; w++)
                if (wv[w] > bv || (wv[w] == bv && wi[w] < bi)) { bv = wv[w]; bi = wi[w]; }
            out[k] = bi;
            vals[bi] = -1e300;
        }
        __syncthreads();
    }
}

// --- merged gather: v packed (19200 blocks) then t padded (24576 blocks) ---
__global__ void gather_all_kernel(const float* __restrict__ vtok, const float* __restrict__ vnfa,
                                  const int* __restrict__ iv, float* __restrict__ vout,
                                  __half* __restrict__ vhi,
                                  const float* __restrict__ ttok, const float* __restrict__ tnfa,
                                  const int* __restrict__ it, float* __restrict__ tout,
                                  __half* __restrict__ thi) {
    int blk = blockIdx.x;
    int t = threadIdx.x;
    if (blk < B_ * K_) {
        int item = blk / K_, r = blk % K_;
        int src = iv[item * K_ + r];
        size_t srow = ((size_t)item * V_ + src) * E_;
        float nf = vnfa[item * V_ + src];
        float4 v = *reinterpret_cast<const float4*>(vtok + srow + t * 4);
        v.x /= nf; v.y /= nf; v.z /= nf; v.w /= nf;
        *reinterpret_cast<float4*>(vout + (size_t)blk * E_ + t * 4) = v;
        __half h[4];
        h[0] = __float2half(v.x); h[1] = __float2half(v.y);
        h[2] = __float2half(v.z); h[3] = __float2half(v.w);
        *reinterpret_cast<uint2*>(vhi + (size_t)blk * E_ + t * 4) = *reinterpret_cast<uint2*>(h);
    } else {
        int bk = blk - B_ * K_;
        int item = bk >> 6, r = bk & 63;
        size_t po = (size_t)(item * KP + r) * E_ + t * 4;
        if (r < K_) {
            int src = it[item * K_ + r];
            size_t srow = ((size_t)item * T_ + src) * E_;
            float nf = tnfa[item * T_ + src];
            float4 v = *reinterpret_cast<const float4*>(ttok + srow + t * 4);
            v.x /= nf; v.y /= nf; v.z /= nf; v.w /= nf;
            *reinterpret_cast<float4*>(tout + (size_t)(item * K_ + r) * E_ + t * 4) = v;
            __half h[4];
            h[0] = __float2half(v.x); h[1] = __float2half(v.y);
            h[2] = __float2half(v.z); h[3] = __float2half(v.w);
            *reinterpret_cast<uint2*>(thi + po) = *reinterpret_cast<uint2*>(h);
        } else {
            uint2 z = {0u, 0u};
            *reinterpret_cast<uint2*>(thi + po) = z;
        }
    }
}

// ===== M-packed mma.sync cross sim: partial rowsum/colmax outputs =====
#define STG_BYTES 16384
#define MAT_BYTES 8192

__global__ void __launch_bounds__(256)
cross_sim_mma_kernel(const __half* __restrict__ Ahi, const __half* __restrict__ Bhi,
                     float* __restrict__ gI, float* __restrict__ gC) {
    extern __shared__ __align__(16) char dyn[];
    __shared__ float rbuf[128][2];
    __shared__ float cpart[4][2][128];
    __shared__ int   blids[4][2];

    const uint32_t sbase = smem_u32(dyn);
    const int tid = threadIdx.x;
    const int wid = tid >> 5;
    const int lane = tid & 31;
    const int by = blockIdx.y;
    const int n0 = blockIdx.x * 128;
    const int warp_m = wid >> 1;
    const int warp_n = wid & 1;

    const __half* gmat[2] = { Ahi + (size_t)by * 128 * E_, Bhi + (size_t)n0 * E_ };

    auto load_stage = [&](int ks, int buf) {
        uint32_t sb = sbase + buf * STG_BYTES;
#pragma unroll
        for (int it = 0; it < 4; it++) {
            int idx = tid + it * 256;
            int mat = idx >> 9, rem = idx & 511;
            int r = rem >> 2, chunk = rem & 3;
            const void* src = gmat[mat] + (size_t)r * E_ + ks * 32 + chunk * 8;
            uint32_t dst = sb + mat * MAT_BYTES + r * 64 + ((chunk ^ (r & 3)) << 4);
            cp16(dst, src);
        }
        CP_COMMIT();
    };

    float acc[2][8][4] = {};
    load_stage(0, 0);

    for (int ks = 0; ks < 8; ks++) {
        CP_WAIT0();
        __syncthreads();
        if (ks + 1 < 8) load_stage(ks + 1, (ks + 1) & 1);

        uint32_t sb = sbase + (ks & 1) * STG_BYTES;
        const int rA = warp_m * 32 + (lane & 15);
        const int khalf = lane >> 4;
#pragma unroll
        for (int kstep = 0; kstep < 2; kstep++) {
            uint32_t ahi[2][4], bhi[4][4];
            int chunk = kstep * 2 + khalf;
#pragma unroll
            for (int mt = 0; mt < 2; mt++) {
                int r = rA + mt * 16;
                uint32_t off = r * 64 + ((chunk ^ (r & 3)) << 4);
                ldsm_x4(ahi[mt], sb + 0 * MAT_BYTES + off);
            }
#pragma unroll
            for (int nt = 0; nt < 4; nt++) {
                int r = warp_n * 64 + nt * 16 + (lane & 15);
                uint32_t off = r * 64 + ((chunk ^ (r & 3)) << 4);
                ldsm_x4(bhi[nt], sb + 1 * MAT_BYTES + off);
            }
#pragma unroll
            for (int mt = 0; mt < 2; mt++)
#pragma unroll
                for (int nt = 0; nt < 4; nt++) {
                    mma16816(acc[mt][nt * 2 + 0], ahi[mt], bhi[nt][0], bhi[nt][2]);
                    if (nt < 3)
                        mma16816(acc[mt][nt * 2 + 1], ahi[mt], bhi[nt][1], bhi[nt][3]);
                }
        }
        __syncthreads();
    }

    // ---- register epilogue ----
    const int l4 = lane & 3, l8 = lane >> 2;
#pragma unroll
    for (int mt = 0; mt < 2; mt++)
#pragma unroll
        for (int ih = 0; ih < 2; ih++) {
            float rm = -1e30f;
#pragma unroll
            for (int nt8 = 0; nt8 < 7; nt8++)
#pragma unroll
                for (int j = 0; j < 2; j++) {
                    int ci = nt8 * 8 + l4 * 2 + j;
                    if (ci < K_) rm = fmaxf(rm, acc[mt][nt8][ih * 2 + j]);
                }
            rm = fmaxf(rm, __shfl_xor_sync(0xffffffffu, rm, 1));
            rm = fmaxf(rm, __shfl_xor_sync(0xffffffffu, rm, 2));
            if (l4 == 0) rbuf[warp_m * 32 + mt * 16 + ih * 8 + l8][warp_n] = rm;
        }
    const int rw0 = by * 128 + warp_m * 32;
    const int s0b = rw0 / 50, s1b = (rw0 + 31) / 50;
    if (lane == 0 && warp_n == 0) { blids[warp_m][0] = s0b; blids[warp_m][1] = s1b; }
    int rb[2][2];
#pragma unroll
    for (int mt = 0; mt < 2; mt++)
#pragma unroll
        for (int ih = 0; ih < 2; ih++) rb[mt][ih] = (rw0 + mt * 16 + ih * 8 + l8) / 50;
#pragma unroll
    for (int s = 0; s < 2; s++) {
        int sb2 = (s == 0) ? s0b : s1b;
#pragma unroll
        for (int nt8 = 0; nt8 < 7; nt8++)
#pragma unroll
            for (int j = 0; j < 2; j++) {
                float cm = -1e30f;
#pragma unroll
                for (int mt = 0; mt < 2; mt++)
#pragma unroll
                    for (int ih = 0; ih < 2; ih++)
                        if (rb[mt][ih] == sb2) cm = fmaxf(cm, acc[mt][nt8][ih * 2 + j]);
                cm = fmaxf(cm, __shfl_xor_sync(0xffffffffu, cm, 4));
                cm = fmaxf(cm, __shfl_xor_sync(0xffffffffu, cm, 8));
                cm = fmaxf(cm, __shfl_xor_sync(0xffffffffu, cm, 16));
                if (l8 == 0) cpart[warp_m][s][warp_n * 64 + nt8 * 8 + l4 * 2 + j] = cm;
            }
    }
    __syncthreads();

    const int b_first = (by * 128) / 50;
    const int b_last  = (by * 128 + 127) / 50;
    if (tid < 8) {
        int bl = tid >> 1, ql = tid & 1;
        int b = b_first + bl;
        if (b <= b_last) {
            int lo = 50 * b - by * 128, hi2 = lo + 50;
            if (lo < 0) lo = 0;
            if (hi2 > 128) hi2 = 128;
            float s = 0.f;
            for (int r = lo; r < hi2; r++) s += rbuf[r][ql];
            gI[((size_t)by * 4 + bl) * Q_ + (blockIdx.x * 2 + ql)] = s;
        }
    } else if (tid >= 128) {
        int j = tid - 128;
        int t = j & 63, ql = j >> 6;
        if (t < K_) {
            int q = blockIdx.x * 2 + ql;
#pragma unroll
            for (int bl = 0; bl < 4; bl++) {
                int b = b_first + bl;
                if (b <= b_last) {
                    float gmv = -1e30f;
#pragma unroll
                    for (int wm = 0; wm < 4; wm++)
#pragma unroll
                        for (int s = 0; s < 2; s++)
                            if (blids[wm][s] == b) gmv = fmaxf(gmv, cpart[wm][s][j]);
                    gC[(((size_t)by * 4 + bl) * Q_ + q) * K_ + t] = gmv;
                }
            }
        }
    }
}

// ===== finalize: combine <=2 block partials per (b,q) -> i2t, t2i =====
__global__ void __launch_bounds__(256)
finalize_kernel(const float* __restrict__ gI, const float* __restrict__ gC,
                float* __restrict__ i2t, float* __restrict__ t2i) {
    __shared__ float s0[128][51];
    __shared__ float s1[128][51];
    int b = blockIdx.x / 3;
    int qg = (blockIdx.x % 3) * 128;
    int tid = threadIdx.x;
    int r0 = 50 * b, r1 = r0 + 49;
    int by0 = r0 >> 7, by1 = r1 >> 7;
    int bl0 = b - (by0 * 128) / 50;
    int bl1 = b - (by1 * 128) / 50;
    const float* src0 = gC + (((size_t)by0 * 4 + bl0) * Q_ + qg) * K_;
    const float* src1 = gC + (((size_t)by1 * 4 + bl1) * Q_ + qg) * K_;
    for (int i = tid; i < 128 * K_; i += 256) {
        int qq = i / K_, tt = i % K_;
        s0[qq][tt] = src0[i];
        s1[qq][tt] = (by1 != by0) ? src1[i] : src0[i];
    }
    __syncthreads();
    if (tid < 128) {
        int q = qg + tid;
        float s = gI[((size_t)by0 * 4 + bl0) * Q_ + q];
        if (by1 != by0) s += gI[((size_t)by1 * 4 + bl1) * Q_ + q];
        i2t[(size_t)b * Q_ + q] = s * (1.0f / 50.0f);
        float ts = 0.f;
        for (int t = 0; t < K_; t++) ts += fmaxf(s0[tid][t], s1[tid][t]);
        t2i[(size_t)b * Q_ + q] = ts * (1.0f / 50.0f);
    }
}

// ---------------- launch ----------------
extern "C" void kernel_launch(void* const* d_in, const int* in_sizes, int n_in,
                              void* d_out, int out_size) {
    const float* visual_cls     = (const float*)d_in[0];
    const float* visual_tokens  = (const float*)d_in[1];
    const float* textual_cls    = (const float*)d_in[2];
    const float* textual_tokens = (const float*)d_in[3];
    const float* Wv     = (const float*)d_in[4];
    const float* bv     = (const float*)d_in[5];
    const float* Wt     = (const float*)d_in[6];
    const float* bt     = (const float*)d_in[7];
    const float* Wv_tok = (const float*)d_in[8];
    const float* bv_tok = (const float*)d_in[9];
    const float* Wt_tok = (const float*)d_in[10];
    const float* bt_tok = (const float*)d_in[11];

    float* out = (float*)d_out;
    float* o_vcls = out;
    float* o_tcls = o_vcls + B_ * E_;
    float* o_vloc = o_tcls + Q_ * E_;
    float* o_tloc = o_vloc + B_ * K_ * E_;
    float* o_i2t  = o_tloc + Q_ * K_ * E_;
    float* o_t2i  = o_i2t + B_ * Q_;

    float *p_vtok, *p_ttok, *p_glob, *p_vnf, *p_tnf, *p_pI, *p_pC;
    double *p_vsim, *p_tsim;
    int *p_iv, *p_it;
    __half *p_Avh, *p_Avl, *p_Ath, *p_Atl, *p_Acvh, *p_Acvl, *p_Acth, *p_Actl;
    __half *p_Wvh, *p_Wvl, *p_Wth, *p_Wtl, *p_Wvth, *p_Wvtl, *p_Wtth, *p_Wttl;
    __half *p_vhi, *p_thi;
    cudaGetSymbolAddress((void**)&p_vtok, g_vtok);
    cudaGetSymbolAddress((void**)&p_ttok, g_ttok);
    cudaGetSymbolAddress((void**)&p_glob, g_glob);
    cudaGetSymbolAddress((void**)&p_vsim, g_vsim);
    cudaGetSymbolAddress((void**)&p_tsim, g_tsim);
    cudaGetSymbolAddress((void**)&p_vnf, g_vnf);
    cudaGetSymbolAddress((void**)&p_tnf, g_tnf);
    cudaGetSymbolAddress((void**)&p_iv, g_iv);
    cudaGetSymbolAddress((void**)&p_it, g_it);
    cudaGetSymbolAddress((void**)&p_pI, g_pI);
    cudaGetSymbolAddress((void**)&p_pC, g_pC);
    cudaGetSymbolAddress((void**)&p_Avh, g_Avh);  cudaGetSymbolAddress((void**)&p_Avl, g_Avl);
    cudaGetSymbolAddress((void**)&p_Ath, g_Ath);  cudaGetSymbolAddress((void**)&p_Atl, g_Atl);
    cudaGetSymbolAddress((void**)&p_Acvh, g_Acvh); cudaGetSymbolAddress((void**)&p_Acvl, g_Acvl);
    cudaGetSymbolAddress((void**)&p_Acth, g_Acth); cudaGetSymbolAddress((void**)&p_Actl, g_Actl);
    cudaGetSymbolAddress((void**)&p_Wvh, g_Wvh);  cudaGetSymbolAddress((void**)&p_Wvl, g_Wvl);
    cudaGetSymbolAddress((void**)&p_Wth, g_Wth);  cudaGetSymbolAddress((void**)&p_Wtl, g_Wtl);
    cudaGetSymbolAddress((void**)&p_Wvth, g_Wvth); cudaGetSymbolAddress((void**)&p_Wvtl, g_Wvtl);
    cudaGetSymbolAddress((void**)&p_Wtth, g_Wtth); cudaGetSymbolAddress((void**)&p_Wttl, g_Wttl);
    cudaGetSymbolAddress((void**)&p_vhi, g_vhi);
    cudaGetSymbolAddress((void**)&p_thi, g_thi);

    // ---- single merged split (inputs + weights) ----
    split_all_kernel<<<(unsigned)((N_ALL + 255) / 256), 256>>>(
        visual_tokens, textual_tokens, visual_cls, textual_cls,
        Wv, Wt, Wv_tok, Wt_tok,
        p_Avh, p_Avl, p_Ath, p_Atl, p_Acvh, p_Acvl, p_Acth, p_Actl,
        p_Wvh, p_Wvl, p_Wth, p_Wtl, p_Wvth, p_Wvtl, p_Wtth, p_Wttl);

    // ---- single merged projection launch (all 4 GEMMs; big first, cls fills the tail) ----
    ProjArgs pa;
    pa.Ah[0] = p_Avh;  pa.Al[0] = p_Avl;  pa.Wh[0] = p_Wvth; pa.Wl[0] = p_Wvtl; pa.bias[0] = bv_tok; pa.C[0] = p_vtok;
    pa.Ah[1] = p_Ath;  pa.Al[1] = p_Atl;  pa.Wh[1] = p_Wtth; pa.Wl[1] = p_Wttl; pa.bias[1] = bt_tok; pa.C[1] = p_ttok;
    pa.Ah[2] = p_Acvh; pa.Al[2] = p_Acvl; pa.Wh[2] = p_Wvh;  pa.Wl[2] = p_Wvl;  pa.bias[2] = bv;     pa.C[2] = o_vcls;
    pa.Ah[3] = p_Acth; pa.Al[3] = p_Actl; pa.Wh[3] = p_Wth;  pa.Wl[3] = p_Wtl;  pa.bias[3] = bt;     pa.C[3] = o_tcls;
    cudaFuncSetAttribute(proj_mma_kernel, cudaFuncAttributeMaxDynamicSharedMemorySize, 2 * PSTG);
    proj_mma_kernel<<<dim3(2, YB_TOTAL), 256, 2 * PSTG>>>(pa);

    norm_rows_kernel<<<(2 * B_ * 32) / 256, 256>>>(o_vcls, p_glob);

    tok_sim_kernel<<<((B_ * V_ + Q_ * T_) * 32) / 256, 256>>>(
        p_vtok, p_ttok, p_glob, p_vsim, p_tsim, p_vnf, p_tnf);

    topk_kernel<<<2 * B_, 256>>>(p_vsim, p_tsim, p_iv, p_it);
    gather_all_kernel<<<B_ * K_ + Q_ * KP, 64>>>(p_vtok, p_vnf, p_iv, o_vloc, p_vhi,
                                                 p_ttok, p_tnf, p_it, o_tloc, p_thi);

    // ---- M-packed single-term fp16 cross sim -> partials -> finalize ----
    const int DSMEM = 2 * STG_BYTES;
    cudaFuncSetAttribute(cross_sim_mma_kernel, cudaFuncAttributeMaxDynamicSharedMemorySize, DSMEM);
    cross_sim_mma_kernel<<<dim3(Q_ / 2, NBY), 256, DSMEM>>>(p_vhi, p_thi, p_pI, p_pC);
    finalize_kernel<<<B_ * 3, 256>>>(p_pI, p_pC, o_i2t, o_t2i);
}